// round 13
// baseline (speedup 1.0000x reference)
#include <cuda_runtime.h>

// CRF Viterbi decode: B=1024, T=512, C=48
// inputs: 0=potentials (B,T,C) f32, 1=sequence_lengths (B,1) i32, 2=transitions (C,C) f32
// output: one_hot(tags, C) f32 (B,T,C)
//
// R13: TWO batches per block (interleaved independent chains per warp).
//  - order_kernel sorts batch ids by descending L; blocks take adjacent pairs
//    (similar L) from a global counter.
//  - 96 threads: pair (2j,2j+1) owns class j for BOTH sequences.
//  - bp arrays for 2 sequences = 49KB -> dynamic shared memory (51KB/block).

#define BB    1024
#define TT    512
#define CC    48
#define HALF  24
#define NTH   (2 * CC)        // 96
#define NBLK  592             // 4 blocks/SM * 148 SMs
#define NPAIR (BB / 2)        // 512

#define SMEM_BYTES (768 + 2 * (TT - 1) * CC + 2 * TT + 16)

__device__ int g_order[BB];
__device__ int g_counter;

// Counting sort of batch ids by descending sequence length; resets counter.
__global__ void order_kernel(const int* __restrict__ seq_len)
{
    __shared__ int hist[TT];
    __shared__ int offs[TT];
    const int tid = threadIdx.x;        // 512 threads

    hist[tid] = 0;
    __syncthreads();

    for (int b = tid; b < BB; b += TT) {
        int L = seq_len[b];
        if (L < 0) L = 0;
        if (L > TT - 1) L = TT - 1;
        atomicAdd(&hist[L], 1);
    }
    __syncthreads();

    if (tid == 0) {
        int acc = 0;
        for (int L = TT - 1; L >= 0; --L) { offs[L] = acc; acc += hist[L]; }
        g_counter = 0;
    }
    __syncthreads();

    for (int b = tid; b < BB; b += TT) {
        int L = seq_len[b];
        if (L < 0) L = 0;
        if (L > TT - 1) L = TT - 1;
        int pos = atomicAdd(&offs[L], 1);
        g_order[pos] = b;
    }
}

// argmax tree over 24 sums with first-max tie-break; strict '>' only ever
// prefers the higher-index side (left subtree holds lower indices).
__device__ __forceinline__ void tree24(const float* __restrict__ v,
                                       float& mv, int& ma)
{
    float val[12]; int id[12];
#pragma unroll
    for (int q = 0; q < 12; ++q) {
        bool p = v[2 * q + 1] > v[2 * q];
        val[q] = p ? v[2 * q + 1] : v[2 * q];
        id[q]  = p ? (2 * q + 1) : (2 * q);
    }
#pragma unroll
    for (int q = 0; q < 6; ++q) {
        bool p = val[2 * q + 1] > val[2 * q];
        val[q] = p ? val[2 * q + 1] : val[2 * q];
        id[q]  = p ? id[2 * q + 1]  : id[2 * q];
    }
#pragma unroll
    for (int q = 0; q < 3; ++q) {
        bool p = val[2 * q + 1] > val[2 * q];
        val[q] = p ? val[2 * q + 1] : val[2 * q];
        id[q]  = p ? id[2 * q + 1]  : id[2 * q];
    }
    bool  p1 = val[1] > val[0];
    float m  = p1 ? val[1] : val[0];
    int   a  = p1 ? id[1]  : id[0];
    bool  p2 = val[2] > m;
    mv = p2 ? val[2] : m;
    ma = p2 ? id[2]  : a;
}

__global__ __launch_bounds__(NTH, 4)
void viterbi_kernel(const float* __restrict__ pot,
                    const int*   __restrict__ seq_len,
                    const float* __restrict__ trans,
                    float*       __restrict__ out)
{
    extern __shared__ unsigned char smem[];
    float*         s_score = (float*)smem;                    // [2 batches][2 bufs][CC]
    unsigned char* s_bpA   = smem + 768;                      // [(TT-1)*CC]
    unsigned char* s_bpB   = s_bpA + (TT - 1) * CC;
    unsigned char* s_tagsA = s_bpB + (TT - 1) * CC;           // [TT]
    unsigned char* s_tagsB = s_tagsA + TT;
    int*           s_misc  = (int*)(s_tagsB + TT);            // [0]=tagA [1]=tagB [2]=pair

    const int tid = threadIdx.x;
    const int j   = tid >> 1;    // class owned by this pair of threads
    const int h   = tid & 1;     // which half of the 48 sources

    // loop-invariant transition column slice: trans[h*24+k][j]
    float c[HALF];
#pragma unroll
    for (int k = 0; k < HALF; ++k)
        c[k] = trans[(h * HALF + k) * CC + j];

    for (;;) {
        __syncthreads();
        if (tid == 0) s_misc[2] = atomicAdd(&g_counter, 1);
        __syncthreads();
        const int p = s_misc[2];
        if (p >= NPAIR) break;

        const int bA = g_order[2 * p];
        const int bB = g_order[2 * p + 1];

        const float* potA = pot + (size_t)bA * TT * CC;
        const float* potB = pot + (size_t)bB * TT * CC;

        int LA = seq_len[bA]; if (LA > TT) LA = TT; if (LA < 1) LA = 1;
        int LB = seq_len[bB]; if (LB > TT) LB = TT; if (LB < 1) LB = 1;
        const int Lmax = LA > LB ? LA : LB;

        float* scA0 = s_score + 0 * CC;   // batch A, buf 0/1
        float* scA1 = s_score + 1 * CC;
        float* scB0 = s_score + 2 * CC;   // batch B, buf 0/1
        float* scB1 = s_score + 3 * CC;

        if (h == 0) { scA0[j] = potA[j]; scB0[j] = potB[j]; }
        __syncthreads();

        int buf = 0;
        for (int t = 1; t < Lmax; ++t) {
            // independent global loads for both sequences (always in-bounds)
            float pvA = potA[t * CC + j];
            float pvB = potB[t * CC + j];

            const float* curA = buf ? scA1 : scA0;
            const float* curB = buf ? scB1 : scB0;
            float*       nxtA = buf ? scA0 : scA1;
            float*       nxtB = buf ? scB0 : scB1;

            // both score slices via float4 LDS (96B-aligned)
            float vA[HALF], vB[HALF];
            {
                const float4* a4 = reinterpret_cast<const float4*>(curA + h * HALF);
                const float4* b4 = reinterpret_cast<const float4*>(curB + h * HALF);
#pragma unroll
                for (int q = 0; q < HALF / 4; ++q) {
                    float4 va = a4[q];
                    float4 vb = b4[q];
                    vA[4 * q + 0] = va.x + c[4 * q + 0];
                    vA[4 * q + 1] = va.y + c[4 * q + 1];
                    vA[4 * q + 2] = va.z + c[4 * q + 2];
                    vA[4 * q + 3] = va.w + c[4 * q + 3];
                    vB[4 * q + 0] = vb.x + c[4 * q + 0];
                    vB[4 * q + 1] = vb.y + c[4 * q + 1];
                    vB[4 * q + 2] = vb.z + c[4 * q + 2];
                    vB[4 * q + 3] = vb.w + c[4 * q + 3];
                }
            }

            // two independent argmax trees (chains interleave at issue)
            float mvA, mvB; int maA, maB;
            tree24(vA, mvA, maA);
            tree24(vB, mvB, maB);
            maA += h * HALF;
            maB += h * HALF;

            // pair combine (lanes 2j,2j+1 in same warp); 4 independent shfls
            float ovA = __shfl_xor_sync(0xFFFFFFFFu, mvA, 1);
            float ovB = __shfl_xor_sync(0xFFFFFFFFu, mvB, 1);
            int   oaA = __shfl_xor_sync(0xFFFFFFFFu, maA, 1);
            int   oaB = __shfl_xor_sync(0xFFFFFFFFu, maB, 1);

            float loAv = h ? ovA : mvA;  int loAa = h ? oaA : maA;
            float hiAv = h ? mvA : ovA;  int hiAa = h ? maA : oaA;
            bool  pA   = hiAv > loAv;
            float bvA  = pA ? hiAv : loAv;
            int   biA  = pA ? hiAa : loAa;

            float loBv = h ? ovB : mvB;  int loBa = h ? oaB : maB;
            float hiBv = h ? mvB : ovB;  int hiBa = h ? maB : oaB;
            bool  pB   = hiBv > loBv;
            float bvB  = pB ? hiBv : loBv;
            int   biB  = pB ? hiBa : loBa;

            // predicated updates (reference masks invalid t with old state)
            if (t < LA) {
                if (h) nxtA[j] = bvA + pvA;
                else   s_bpA[(t - 1) * CC + j] = (unsigned char)biA;
            }
            if (t < LB) {
                if (h) nxtB[j] = bvB + pvB;
                else   s_bpB[(t - 1) * CC + j] = (unsigned char)biB;
            }
            buf ^= 1;
            __syncthreads();
        }

        // final score buffers: parity of last written step per batch
        const float* finA = ((LA - 1) & 1) ? scA1 : scA0;
        const float* finB = ((LB - 1) & 1) ? scB1 : scB0;

        // final argmax (first-max wins); two lanes in different warps
        if (tid == 0) {
            float bestv = finA[0]; int tag = 0;
#pragma unroll
            for (int i = 1; i < CC; ++i) {
                float v = finA[i];
                if (v > bestv) { bestv = v; tag = i; }
            }
            s_misc[0] = tag;
        }
        if (tid == 32) {
            float bestv = finB[0]; int tag = 0;
#pragma unroll
            for (int i = 1; i < CC; ++i) {
                float v = finB[i];
                if (v > bestv) { bestv = v; tag = i; }
            }
            s_misc[1] = tag;
        }
        __syncthreads();

        const int tagA0 = s_misc[0];
        const int tagB0 = s_misc[1];

        // parallel identity-tail fill, split across the two half-blocks
        if (tid < CC) {
            for (int t = LA - 1 + tid; t < TT; t += CC) s_tagsA[t] = (unsigned char)tagA0;
        } else {
            for (int t = LB - 1 + (tid - CC); t < TT; t += CC) s_tagsB[t] = (unsigned char)tagB0;
        }

        // serial backtracks in different warps (parallel pointer chases)
        if (tid == 0) {
            int tag = tagA0;
            for (int t = LA - 1; t >= 1; --t) {
                tag = s_bpA[(t - 1) * CC + tag];
                s_tagsA[t - 1] = (unsigned char)tag;
            }
        }
        if (tid == 32) {
            int tag = tagB0;
            for (int t = LB - 1; t >= 1; --t) {
                tag = s_bpB[(t - 1) * CC + tag];
                s_tagsB[t - 1] = (unsigned char)tag;
            }
        }
        __syncthreads();

        // one-hot output, float4 coalesced, both rows
        {
            float4* ob = reinterpret_cast<float4*>(out + (size_t)bA * TT * CC);
            const int NQ = TT * (CC / 4);
            for (int q = tid; q < NQ; q += NTH) {
                int t   = q / (CC / 4);
                int r   = q % (CC / 4);
                int tg  = s_tagsA[t];
                int e   = r * 4;
                float4 v;
                v.x = (e + 0 == tg) ? 1.0f : 0.0f;
                v.y = (e + 1 == tg) ? 1.0f : 0.0f;
                v.z = (e + 2 == tg) ? 1.0f : 0.0f;
                v.w = (e + 3 == tg) ? 1.0f : 0.0f;
                ob[q] = v;
            }
        }
        {
            float4* ob = reinterpret_cast<float4*>(out + (size_t)bB * TT * CC);
            const int NQ = TT * (CC / 4);
            for (int q = tid; q < NQ; q += NTH) {
                int t   = q / (CC / 4);
                int r   = q % (CC / 4);
                int tg  = s_tagsB[t];
                int e   = r * 4;
                float4 v;
                v.x = (e + 0 == tg) ? 1.0f : 0.0f;
                v.y = (e + 1 == tg) ? 1.0f : 0.0f;
                v.z = (e + 2 == tg) ? 1.0f : 0.0f;
                v.w = (e + 3 == tg) ? 1.0f : 0.0f;
                ob[q] = v;
            }
        }
    }
}

extern "C" void kernel_launch(void* const* d_in, const int* in_sizes, int n_in,
                              void* d_out, int out_size)
{
    const float* pot    = (const float*)d_in[0];
    const int*   seqlen = (const int*)d_in[1];
    const float* trans  = (const float*)d_in[2];
    float*       out    = (float*)d_out;

    cudaFuncSetAttribute(viterbi_kernel,
                         cudaFuncAttributeMaxDynamicSharedMemorySize, SMEM_BYTES);

    order_kernel<<<1, TT>>>(seqlen);
    viterbi_kernel<<<NBLK, NTH, SMEM_BYTES>>>(pot, seqlen, trans, out);
}

// round 14
// speedup vs baseline: 1.2048x; 1.2048x over previous
#include <cuda_runtime.h>

// CRF Viterbi decode: B=1024, T=512, C=48
// R14: ONE WARP PER SEQUENCE, barrier-free (syncwarp only).
// Lane k owns class k; lanes 0-15 additionally own class 32+k.
// 1024 blocks x 32 threads, 25KB smem each -> whole batch co-resident.

#define BB 1024
#define TT 512
#define CC 48

__global__ __launch_bounds__(32, 8)
void viterbi_kernel(const float* __restrict__ pot,
                    const int*   __restrict__ seq_len,
                    const float* __restrict__ trans,
                    float*       __restrict__ out)
{
    __shared__ float         s_score[2][CC];
    __shared__ unsigned char s_bp[(TT - 1) * CC];
    __shared__ unsigned char s_tags[TT];

    const int b  = blockIdx.x;
    const int k  = threadIdx.x;          // lane
    const int j0 = k;                    // first owned class (all lanes)
    const bool two = (k < 16);
    const int j1 = two ? (32 + k) : 0;   // second owned class (safe index)

    // transition columns in registers
    float c0[CC], c1[CC];
#pragma unroll
    for (int i = 0; i < CC; ++i) c0[i] = trans[i * CC + j0];
#pragma unroll
    for (int i = 0; i < CC; ++i) c1[i] = trans[i * CC + j1];

    const float* potb = pot + (size_t)b * TT * CC;
    int L = seq_len[b];
    if (L > TT) L = TT;
    if (L < 1)  L = 1;

    // init scores
    s_score[0][j0] = potb[j0];
    if (two) s_score[0][j1] = potb[j1];

    // depth-3 prefetch of potentials for both owned classes (clamped indices)
    float pa0, pa1, pa2, pb0, pb1, pb2;
    {
        int i1 = 1 < TT - 1 ? 1 : TT - 1;
        int i2 = 2 < TT - 1 ? 2 : TT - 1;
        int i3 = 3 < TT - 1 ? 3 : TT - 1;
        pa0 = potb[i1 * CC + j0]; pb0 = potb[i1 * CC + j1];
        pa1 = potb[i2 * CC + j0]; pb1 = potb[i2 * CC + j1];
        pa2 = potb[i3 * CC + j0]; pb2 = potb[i3 * CC + j1];
    }
    __syncwarp();

    int buf = 0;
    for (int t = 1; t < L; ++t) {
        float pvA = pa0, pvB = pb0;
        pa0 = pa1; pa1 = pa2;
        pb0 = pb1; pb1 = pb2;
        int tl = t + 3; if (tl > TT - 1) tl = TT - 1;
        pa2 = potb[tl * CC + j0];
        pb2 = potb[tl * CC + j1];

        // per-class argmax over 48 sources, chunked 4-wide, first-max exact.
        const float4* s4 = reinterpret_cast<const float4*>(s_score[buf]);
        float w0v[12], w1v[12]; int w0a[12], w1a[12];
#pragma unroll
        for (int q = 0; q < 12; ++q) {
            float4 sv = s4[q];           // broadcast LDS (same addr all lanes)
            int base = 4 * q;
            // class j0
            {
                float v0 = sv.x + c0[base + 0];
                float v1 = sv.y + c0[base + 1];
                float v2 = sv.z + c0[base + 2];
                float v3 = sv.w + c0[base + 3];
                bool pa = v1 > v0;  float m01 = pa ? v1 : v0;  int a01 = pa ? base + 1 : base + 0;
                bool pb = v3 > v2;  float m23 = pb ? v3 : v2;  int a23 = pb ? base + 3 : base + 2;
                bool pc = m23 > m01;
                w0v[q] = pc ? m23 : m01;
                w0a[q] = pc ? a23 : a01;
            }
            // class j1
            {
                float v0 = sv.x + c1[base + 0];
                float v1 = sv.y + c1[base + 1];
                float v2 = sv.z + c1[base + 2];
                float v3 = sv.w + c1[base + 3];
                bool pa = v1 > v0;  float m01 = pa ? v1 : v0;  int a01 = pa ? base + 1 : base + 0;
                bool pb = v3 > v2;  float m23 = pb ? v3 : v2;  int a23 = pb ? base + 3 : base + 2;
                bool pc = m23 > m01;
                w1v[q] = pc ? m23 : m01;
                w1a[q] = pc ? a23 : a01;
            }
        }
        // winner trees 12->6->3->1 (ascending, strict '>' prefers higher chunk)
        float bv0, bv1; int ba0, ba1;
        {
#pragma unroll
            for (int q = 0; q < 6; ++q) {
                bool p = w0v[2 * q + 1] > w0v[2 * q];
                w0v[q] = p ? w0v[2 * q + 1] : w0v[2 * q];
                w0a[q] = p ? w0a[2 * q + 1] : w0a[2 * q];
            }
#pragma unroll
            for (int q = 0; q < 3; ++q) {
                bool p = w0v[2 * q + 1] > w0v[2 * q];
                w0v[q] = p ? w0v[2 * q + 1] : w0v[2 * q];
                w0a[q] = p ? w0a[2 * q + 1] : w0a[2 * q];
            }
            bool p1 = w0v[1] > w0v[0];
            float m = p1 ? w0v[1] : w0v[0];
            int   a = p1 ? w0a[1] : w0a[0];
            bool p2 = w0v[2] > m;
            bv0 = p2 ? w0v[2] : m;
            ba0 = p2 ? w0a[2] : a;
        }
        {
#pragma unroll
            for (int q = 0; q < 6; ++q) {
                bool p = w1v[2 * q + 1] > w1v[2 * q];
                w1v[q] = p ? w1v[2 * q + 1] : w1v[2 * q];
                w1a[q] = p ? w1a[2 * q + 1] : w1a[2 * q];
            }
#pragma unroll
            for (int q = 0; q < 3; ++q) {
                bool p = w1v[2 * q + 1] > w1v[2 * q];
                w1v[q] = p ? w1v[2 * q + 1] : w1v[2 * q];
                w1a[q] = p ? w1a[2 * q + 1] : w1a[2 * q];
            }
            bool p1 = w1v[1] > w1v[0];
            float m = p1 ? w1v[1] : w1v[0];
            int   a = p1 ? w1a[1] : w1a[0];
            bool p2 = w1v[2] > m;
            bv1 = p2 ? w1v[2] : m;
            ba1 = p2 ? w1a[2] : a;
        }

        // write new scores + backpointers
        float* nxt = s_score[buf ^ 1];
        unsigned char* bpr = s_bp + (t - 1) * CC;
        nxt[j0] = bv0 + pvA;
        bpr[j0] = (unsigned char)ba0;
        if (two) {
            nxt[j1] = bv1 + pvB;
            bpr[j1] = (unsigned char)ba1;
        }
        buf ^= 1;
        __syncwarp();
    }

    // final argmax (lane 0, ascending strict '>' = first-max)
    __shared__ int s_lasttag;
    if (k == 0) {
        const float* fin = s_score[buf];
        float bestv = fin[0]; int tag = 0;
#pragma unroll
        for (int i = 1; i < CC; ++i) {
            float v = fin[i];
            if (v > bestv) { bestv = v; tag = i; }
        }
        s_lasttag = tag;
    }
    __syncwarp();

    const int tag0 = s_lasttag;
    // identity tail: t in [L-1, TT-1]
    for (int t = L - 1 + k; t < TT; t += 32) s_tags[t] = (unsigned char)tag0;

    // backtrack (lane 0, smem pointer chase)
    if (k == 0) {
        int tag = tag0;
        for (int t = L - 1; t >= 1; --t) {
            tag = s_bp[(t - 1) * CC + tag];
            s_tags[t - 1] = (unsigned char)tag;
        }
    }
    __syncwarp();

    // one-hot output: 6144 float4 per row, 192 per lane, coalesced
    float4* ob = reinterpret_cast<float4*>(out + (size_t)b * TT * CC);
    const int NQ = TT * (CC / 4);
    for (int q = k; q < NQ; q += 32) {
        int t   = q / (CC / 4);
        int r   = q % (CC / 4);
        int tg  = s_tags[t];
        int e   = r * 4;
        float4 v;
        v.x = (e + 0 == tg) ? 1.0f : 0.0f;
        v.y = (e + 1 == tg) ? 1.0f : 0.0f;
        v.z = (e + 2 == tg) ? 1.0f : 0.0f;
        v.w = (e + 3 == tg) ? 1.0f : 0.0f;
        ob[q] = v;
    }
}

extern "C" void kernel_launch(void* const* d_in, const int* in_sizes, int n_in,
                              void* d_out, int out_size)
{
    const float* pot    = (const float*)d_in[0];
    const int*   seqlen = (const int*)d_in[1];
    const float* trans  = (const float*)d_in[2];
    float*       out    = (float*)d_out;

    viterbi_kernel<<<BB, 32>>>(pot, seqlen, trans, out);
}